// round 6
// baseline (speedup 1.0000x reference)
#include <cuda_runtime.h>

#define NBATCH 4
#define NTOK   4096
#define DDIM   16
#define NB     64                    /* bins */
#define XLO    (-6.0f)
#define BINW   0.1875f               /* 12/64, exact in fp32 */
#define INVW   (64.0f / 12.0f)
#define L2E    1.44269504088896f
#define GX     32                    /* blocks per batch */
#define NTHR   128                   /* one thread per row */
#define RPB    (NTOK / GX)           /* 128 rows / block */

__device__ __forceinline__ float ex2f(float v) {
    float r;
    asm("ex2.approx.ftz.f32 %0, %1;" : "=f"(r) : "f"(v));
    return r;
}

__global__ __launch_bounds__(NTHR, 1)
void fused_attn_kernel(const float* __restrict__ x,
                       const float* __restrict__ wq,
                       const float* __restrict__ wk,
                       const float* __restrict__ wv,
                       const float* __restrict__ wo,
                       float* __restrict__ out)
{
    // per-block private moment histogram: 6 moments x 64 bins
    __shared__ float h[6][NB];
    __shared__ float4 sha[NB];       // (n, M1, M2, M3)
    __shared__ float4 shb[NB];       // (M4, M5, 0, 0)

    const int b   = blockIdx.y;
    const int blk = blockIdx.x;
    const int tid = threadIdx.x;
    const float* xb = x + b * NTOK;

    // ---- zero the histogram ----
    #pragma unroll
    for (int i = tid; i < 6 * NB; i += NTHR)
        (&h[0][0])[i] = 0.f;

    // ---- tiny dot products (redundant per thread, L1 broadcast) ----
    float c = 0.f, g = 0.f;
    #pragma unroll
    for (int i = 0; i < DDIM; i++) {
        c = fmaf(wq[i], wk[i], c);
        g = fmaf(wv[i], wo[i], g);
    }
    c *= 0.25f;   // 1/sqrt(ATTN_DIM), TAU = 1

    __syncthreads();

    // ---- phase A: build the full batch histogram LOCALLY (smem atomics).
    // Redundant across blocks, but removes all inter-CTA synchronization.
    {
        const float4* x4 = reinterpret_cast<const float4*>(xb);
        #pragma unroll
        for (int i = tid; i < NTOK / 4; i += NTHR) {
            float4 vv = x4[i];
            #pragma unroll
            for (int j = 0; j < 4; j++) {
                float v = (j == 0) ? vv.x : (j == 1) ? vv.y : (j == 2) ? vv.z : vv.w;
                int k = __float2int_rz((v - XLO) * INVW);
                k = max(0, min(NB - 1, k));
                float bc = fmaf((float)k + 0.5f, BINW, XLO);
                float d  = v - bc;
                float d2 = d * d;
                float d3 = d2 * d;
                atomicAdd(&h[0][k], 1.0f);
                atomicAdd(&h[1][k], d);
                atomicAdd(&h[2][k], d2);
                atomicAdd(&h[3][k], d3);
                atomicAdd(&h[4][k], d2 * d2);
                atomicAdd(&h[5][k], d3 * d2);
            }
        }
    }
    __syncthreads();

    // ---- repack into float4 for the hot loop ----
    if (tid < NB) {
        sha[tid] = make_float4(h[0][tid], h[1][tid], h[2][tid], h[3][tid]);
        shb[tid] = make_float4(h[4][tid], h[5][tid], 0.f, 0.f);
    }
    __syncthreads();

    // ---- phase C: row-per-thread softmax-weighted sum over 64 bins ----
    {
        const int row = blk * RPB + tid;
        const float v = xb[row];

        const float t  = c * v;
        const float u2 = 0.5f * t * t;
        const float u3 = u2 * t * (1.f / 3.f);
        const float u4 = u3 * t * 0.25f;
        const float u5 = u4 * t * 0.2f;
        const float A  = t * L2E;
        const float C0 = -fabsf(A) * 6.0f;      // max-shift: arg <= 0 always

        // running-product exponential over bin centers
        float e = ex2f(fmaf(A, XLO + 0.5f * BINW, C0));
        const float f = ex2f(A * BINW);

        float s0 = 0.f, s1 = 0.f;
        float bb = XLO + 0.5f * BINW;

        #pragma unroll
        for (int k = 0; k < NB; k++) {
            float4 ma = sha[k];                  // warp-uniform broadcast
            float4 mb = shb[k];
            float P = fmaf(t,  ma.y, ma.x);
            P       = fmaf(u2, ma.z, P);
            P       = fmaf(u3, ma.w, P);
            P       = fmaf(u4, mb.x, P);
            P       = fmaf(u5, mb.y, P);
            float Q = fmaf(t,  ma.z, ma.y);
            Q       = fmaf(u2, ma.w, Q);
            Q       = fmaf(u3, mb.x, Q);
            Q       = fmaf(u4, mb.y, Q);
            float r = fmaf(bb, P, Q);
            s0 = fmaf(e, P, s0);
            s1 = fmaf(e, r, s1);
            e *= f;
            bb += BINW;
        }

        out[b * NTOK + row] = g * s1 / s0;
    }
}

extern "C" void kernel_launch(void* const* d_in, const int* in_sizes, int n_in,
                              void* d_out, int out_size)
{
    const float* x  = (const float*)d_in[0];
    const float* wq = (const float*)d_in[1];
    const float* wk = (const float*)d_in[2];
    const float* wv = (const float*)d_in[3];
    const float* wo = (const float*)d_in[4];
    float* out = (float*)d_out;

    fused_attn_kernel<<<dim3(GX, NBATCH), NTHR>>>(x, wq, wk, wv, wo, out);
}

// round 7
// speedup vs baseline: 5.0119x; 5.0119x over previous
#include <cuda_runtime.h>

#define NBATCH 4
#define NTOK   4096
#define DDIM   16
#define NB     64                    /* bins */
#define XLO    (-6.0f)
#define BINW   0.1875f               /* 12/64, exact in fp32 */
#define INVW   (64.0f / 12.0f)
#define L2E    1.44269504088896f
#define GX     32                    /* blocks per batch */
#define NTHR   128                   /* one thread per row / value */
#define RPB    (NTOK / GX)           /* 128 rows per block */

// Per-(batch,slot) partial moment histograms, written (not accumulated) by k1.
// Layout per slot: 128 float4 — [0..63] = (n,M1,M2,M3) of bin j, [64..127] = (M4,M5,0,0).
__device__ float4 g_part[NBATCH][GX][2 * NB];

__device__ __forceinline__ float ex2f(float v) {
    float r;
    asm("ex2.approx.ftz.f32 %0, %1;" : "=f"(r) : "f"(v));
    return r;
}

// ---------------- kernel 1: per-block partial histograms (128 values each) ----------------
__global__ __launch_bounds__(NTHR, 1)
void hist_kernel(const float* __restrict__ x)
{
    __shared__ float h[6][NB];

    const int b   = blockIdx.y;
    const int blk = blockIdx.x;
    const int tid = threadIdx.x;

    // zero the tiny smem histogram (384 floats)
    #pragma unroll
    for (int i = tid; i < 6 * NB; i += NTHR)
        (&h[0][0])[i] = 0.f;
    __syncthreads();

    // one value per thread -> 6 smem atomics (low contention: <=128 values over 64 bins)
    {
        const float v = x[b * NTOK + blk * RPB + tid];
        int k = __float2int_rz((v - XLO) * INVW);
        k = max(0, min(NB - 1, k));
        float bc = fmaf((float)k + 0.5f, BINW, XLO);
        float d  = v - bc;
        float d2 = d * d;
        float d3 = d2 * d;
        atomicAdd(&h[0][k], 1.0f);
        atomicAdd(&h[1][k], d);
        atomicAdd(&h[2][k], d2);
        atomicAdd(&h[3][k], d3);
        atomicAdd(&h[4][k], d2 * d2);
        atomicAdd(&h[5][k], d3 * d2);
    }
    __syncthreads();

    // write the 2KB partial to this block's private slot (plain stores)
    float4 v4;
    if (tid < NB)
        v4 = make_float4(h[0][tid], h[1][tid], h[2][tid], h[3][tid]);
    else
        v4 = make_float4(h[4][tid - NB], h[5][tid - NB], 0.f, 0.f);
    g_part[b][blk][tid] = v4;
}

// ---------------- kernel 2: sum partials + per-row softmax-weighted sums ----------------
__global__ __launch_bounds__(NTHR, 1)
void main_kernel(const float* __restrict__ x,
                 const float* __restrict__ wq,
                 const float* __restrict__ wk,
                 const float* __restrict__ wv,
                 const float* __restrict__ wo,
                 float* __restrict__ out)
{
    __shared__ float4 sha[NB];       // (n, M1, M2, M3)
    __shared__ float4 shb[NB];       // (M4, M5, -, -)

    const int b   = blockIdx.y;
    const int blk = blockIdx.x;
    const int tid = threadIdx.x;
    const float* xb = x + b * NTOK;

    // ---- tiny dot products (redundant per thread, L1 broadcast) ----
    float c = 0.f, g = 0.f;
    #pragma unroll
    for (int i = 0; i < DDIM; i++) {
        c = fmaf(wq[i], wk[i], c);
        g = fmaf(wv[i], wo[i], g);
    }
    c *= 0.25f;   // 1/sqrt(ATTN_DIM), TAU = 1

    // ---- sum this thread's float4 column across the 32 slots (L2 hits, high MLP) ----
    {
        float4 a0 = make_float4(0.f, 0.f, 0.f, 0.f);
        float4 a1 = make_float4(0.f, 0.f, 0.f, 0.f);
        float4 a2 = make_float4(0.f, 0.f, 0.f, 0.f);
        float4 a3 = make_float4(0.f, 0.f, 0.f, 0.f);
        #pragma unroll
        for (int s = 0; s < GX; s += 4) {
            float4 p0 = g_part[b][s + 0][tid];
            float4 p1 = g_part[b][s + 1][tid];
            float4 p2 = g_part[b][s + 2][tid];
            float4 p3 = g_part[b][s + 3][tid];
            a0.x += p0.x; a0.y += p0.y; a0.z += p0.z; a0.w += p0.w;
            a1.x += p1.x; a1.y += p1.y; a1.z += p1.z; a1.w += p1.w;
            a2.x += p2.x; a2.y += p2.y; a2.z += p2.z; a2.w += p2.w;
            a3.x += p3.x; a3.y += p3.y; a3.z += p3.z; a3.w += p3.w;
        }
        float4 a = make_float4(a0.x + a1.x + a2.x + a3.x,
                               a0.y + a1.y + a2.y + a3.y,
                               a0.z + a1.z + a2.z + a3.z,
                               a0.w + a1.w + a2.w + a3.w);
        if (tid < NB) sha[tid] = a;
        else          shb[tid - NB] = a;
    }
    __syncthreads();

    // ---- phase C: row-per-thread softmax-weighted sum over 64 bins ----
    {
        const int row = blk * RPB + tid;
        const float v = xb[row];

        const float t  = c * v;
        const float u2 = 0.5f * t * t;
        const float u3 = u2 * t * (1.f / 3.f);
        const float u4 = u3 * t * 0.25f;
        const float u5 = u4 * t * 0.2f;
        const float A  = t * L2E;
        const float C0 = -fabsf(A) * 6.0f;      // max-shift: arg <= 0 always

        // running-product exponential over bin centers
        float e = ex2f(fmaf(A, XLO + 0.5f * BINW, C0));
        const float f = ex2f(A * BINW);

        float s0 = 0.f, s1 = 0.f;
        float bb = XLO + 0.5f * BINW;

        #pragma unroll
        for (int k = 0; k < NB; k++) {
            float4 ma = sha[k];                  // warp-uniform broadcast
            float4 mb = shb[k];
            float P = fmaf(t,  ma.y, ma.x);
            P       = fmaf(u2, ma.z, P);
            P       = fmaf(u3, ma.w, P);
            P       = fmaf(u4, mb.x, P);
            P       = fmaf(u5, mb.y, P);
            float Q = fmaf(t,  ma.z, ma.y);
            Q       = fmaf(u2, ma.w, Q);
            Q       = fmaf(u3, mb.x, Q);
            Q       = fmaf(u4, mb.y, Q);
            float r = fmaf(bb, P, Q);
            s0 = fmaf(e, P, s0);
            s1 = fmaf(e, r, s1);
            e *= f;
            bb += BINW;
        }

        out[b * NTOK + row] = g * s1 / s0;
    }
}

extern "C" void kernel_launch(void* const* d_in, const int* in_sizes, int n_in,
                              void* d_out, int out_size)
{
    const float* x  = (const float*)d_in[0];
    const float* wq = (const float*)d_in[1];
    const float* wk = (const float*)d_in[2];
    const float* wv = (const float*)d_in[3];
    const float* wo = (const float*)d_in[4];
    float* out = (float*)d_out;

    hist_kernel<<<dim3(GX, NBATCH), NTHR>>>(x);
    main_kernel<<<dim3(GX, NBATCH), NTHR>>>(x, wq, wk, wv, wo, out);
}